// round 7
// baseline (speedup 1.0000x reference)
#include <cuda_runtime.h>
#include <cuda_bf16.h>
#include <cstdint>

// ---------------- problem constants ----------------
#define BQ 2
#define TQ 8
#define YQ 128
#define XQ 128
#define CIN 128
#define COUTQ 64
#define YOQ 255
#define XOQ 255
#define NPTS 262144
#define NCELL (BQ*TQ*YQ*XQ)
#define NSITE (BQ*TQ*YOQ*XOQ)
#define EPSQ 1e-5f

// ---------------- device scratch ----------------
__device__ __align__(16) float g_A[(size_t)NCELL * CIN];   // fp32 cell grid (tf32-rounded in place)
__device__ __align__(16) int   g_occ[NCELL];
__device__ unsigned char       g_mask[NSITE];
__device__ __align__(16) float g_sum[COUTQ];
__device__ __align__(16) float g_sumsq[COUTQ];
__device__ int                 g_nactive;
__device__ __align__(16) float g_scale[COUTQ];
__device__ __align__(16) float g_shift[COUTQ];
// tf32(fp32-bit) weights, linear [27 koff][co][ci]
__device__ __align__(16) uint32_t g_Wt32[27 * COUTQ * CIN];

// ---------------- helpers ----------------
__device__ __forceinline__ uint32_t smem_u32(const void* p) {
    uint32_t a;
    asm("{ .reg .u64 t; cvta.to.shared.u64 t, %1; cvt.u32.u64 %0, t; }" : "=r"(a) : "l"(p));
    return a;
}
__device__ __forceinline__ void ldsm4(uint32_t* r, uint32_t addr) {
    asm volatile("ldmatrix.sync.aligned.m8n8.x4.shared.b16 {%0,%1,%2,%3}, [%4];"
        : "=r"(r[0]), "=r"(r[1]), "=r"(r[2]), "=r"(r[3]) : "r"(addr));
}
__device__ __forceinline__ void mma_tf32(float* c, const uint32_t* a, uint32_t b0, uint32_t b1) {
    asm volatile("mma.sync.aligned.m16n8k8.row.col.f32.tf32.tf32.f32 "
        "{%0,%1,%2,%3}, {%4,%5,%6,%7}, {%8,%9}, {%0,%1,%2,%3};"
        : "+f"(c[0]), "+f"(c[1]), "+f"(c[2]), "+f"(c[3])
        : "r"(a[0]), "r"(a[1]), "r"(a[2]), "r"(a[3]), "r"(b0), "r"(b1));
}
__device__ __forceinline__ uint32_t f2tf32(float x) {
    uint32_t t;
    asm("cvt.rna.tf32.f32 %0, %1;" : "=r"(t) : "f"(x));
    return t;
}
#define CPASYNC16(sa, gp) \
    asm volatile("cp.async.cg.shared.global [%0], [%1], 16;" :: "r"(sa), "l"(gp))
#define CPCOMMIT() asm volatile("cp.async.commit_group;" ::: "memory")
#define CPWAIT(n)  asm volatile("cp.async.wait_group %0;" :: "n"(n) : "memory")

// 256B rows of 16 16B-chunks, XOR-swizzled within 8-chunk groups.
__device__ __forceinline__ uint32_t chunk_off(int c16, int rs) {
    return (uint32_t)(((c16 & 8) << 4) | (((c16 & 7) ^ rs) << 4));
}

// ---------------- K0: zero scratch ----------------
__global__ void k_zero() {
    int idx = blockIdx.x * 256 + threadIdx.x;
    if (idx < NCELL * CIN / 4)
        ((float4*)g_A)[idx] = make_float4(0.f, 0.f, 0.f, 0.f);
    if (idx < NCELL / 4)
        ((int4*)g_occ)[idx] = make_int4(0, 0, 0, 0);
    if (idx < COUTQ) { g_sum[idx] = 0.f; g_sumsq[idx] = 0.f; }
    if (idx == 0) g_nactive = 0;
}

// ---------------- K0b: tf32-round + transpose weights [koff][ci][co] -> [koff][co][ci] ----------------
__global__ void k_prepw(const float* __restrict__ W) {
    int i = blockIdx.x * 256 + threadIdx.x;
    if (i >= 27 * CIN * COUTQ) return;
    int koff = i / (CIN * COUTQ);
    int r    = i % (CIN * COUTQ);
    int ci = r / COUTQ, co = r % COUTQ;
    g_Wt32[(size_t)koff * 8192 + co * CIN + ci] = f2tf32(W[i]);
}

// ---------------- K1: scatter points ----------------
__global__ void k_scatter(const float* __restrict__ feats,
                          const int* __restrict__ cb, const int* __restrict__ ct,
                          const int* __restrict__ cy, const int* __restrict__ cx) {
    int i = blockIdx.x * 256 + threadIdx.x;
    if (i >= NPTS * 32) return;
    int p  = i >> 5;
    int c4 = i & 31;
    int cell = ((cb[p] * TQ + ct[p]) * YQ + cy[p]) * XQ + cx[p];
    float4 v = ((const float4*)feats)[p * 32 + c4];
    float* dst = &g_A[(size_t)cell * CIN + c4 * 4];
    atomicAdd(dst + 0, v.x);
    atomicAdd(dst + 1, v.y);
    atomicAdd(dst + 2, v.z);
    atomicAdd(dst + 3, v.w);
    if (c4 == 0) atomicAdd(&g_occ[cell], 1);
}

// ---------------- K1b: tf32-round g_A in place ----------------
__global__ void k_convert() {
    int i = blockIdx.x * 256 + threadIdx.x;
    float4 v = ((const float4*)g_A)[i];
    v.x = __uint_as_float(f2tf32(v.x));
    v.y = __uint_as_float(f2tf32(v.y));
    v.z = __uint_as_float(f2tf32(v.z));
    v.w = __uint_as_float(f2tf32(v.w));
    ((float4*)g_A)[i] = v;
}

// ---------------- K2: K-split stage-pipelined tf32 conv ----------------
// Stage (80KB): A-half [0,32K)  (128 cells x 256B, swizzled)
//               W-half at 32768 + kx*16384  (64 co x 256B, swizzled)
// 2 stages double-buffered. One commit group per stage; depth-2 pipeline.
#define STG 81920
#define CONV_DYN_SMEM (2 * STG)

__device__ __forceinline__ void fetch_stage(uint32_t dst, int slab, int koff, int kh, int tid) {
    const char* gA = (const char*)g_A + (size_t)slab * 65536 + kh * 256;
#pragma unroll
    for (int j = 0; j < 4; j++) {
        int e = tid + j * 512;
        int cell = e >> 4, c16 = e & 15;
        CPASYNC16(dst + cell * 256 + chunk_off(c16, cell & 7),
                  gA + (size_t)cell * 512 + c16 * 16);
    }
    const char* gW = (const char*)g_Wt32 + (size_t)koff * 32768 + kh * 256;
#pragma unroll
    for (int j = 0; j < 6; j++) {
        int e = tid + j * 512;
        int kx = e >> 10, w = e & 1023;
        int co = w >> 4, c16 = w & 15;
        CPASYNC16(dst + 32768 + kx * 16384 + co * 256 + chunk_off(c16, co & 7),
                  gW + (size_t)kx * 32768 + (size_t)co * 512 + c16 * 16);
    }
    CPCOMMIT();
}

__global__ void __launch_bounds__(512, 1) k_conv(float* __restrict__ out) {
    extern __shared__ char smem[];
    const uint32_t sb = smem_u32(smem);
    const int tid = threadIdx.x, wid = tid >> 5, lane = tid & 31;
    const int half = wid >> 3, wm = wid & 7;

    const int bid = blockIdx.x;
    const int oy = bid % YOQ;
    const int bt = bid / YOQ;
    const int b = bt >> 3, ot = bt & 7;

    // y taps
    int nky, cys[2], kys[2];
    if ((oy & 1) == 0) { nky = 1; cys[0] = oy >> 1;       kys[0] = 1; }
    else               { nky = 2; cys[0] = (oy + 1) >> 1; kys[0] = 0;
                                  cys[1] = (oy - 1) >> 1; kys[1] = 2; }

    // stage list (iter x 2 K-halves)
    int nStage = 0;
    int slabS[12], koffS[12], khS[12];
    for (int kt = 0; kt < 3; kt++) {
        int ctv = ot + 1 - kt;
        if (ctv < 0 || ctv >= TQ) continue;
        for (int yt = 0; yt < nky; yt++) {
            int slab = (b * TQ + ctv) * YQ + cys[yt];
            int koff = (kt * 3 + kys[yt]) * 3;
            for (int kh = 0; kh < 2; kh++) {
                slabS[nStage] = slab; koffS[nStage] = koff; khS[nStage] = kh;
                nStage++;
            }
        }
    }

    // ldmatrix geometry (256B rows)
    const int r0 = wm << 4;
    const int matL = lane >> 3, rr = lane & 7;
    const int rA0 = r0 + rr + ((matL & 1) << 3);
    const int rA1 = rA0 + 1;                  // row 128 reads W region: finite garbage, masked
    const int cSel = matL >> 1;
    const uint32_t baseA0 = (uint32_t)rA0 * 256; const int rs0 = rA0 & 7;
    const uint32_t baseA1 = (uint32_t)rA1 * 256; const int rs1 = rA1 & 7;
    const int rowB = half * 32 + rr + ((matL & 1) << 3);
    const uint32_t baseB0 = (uint32_t)rowB * 256;
    const uint32_t baseB1 = baseB0 + 16 * 256;
    const int rsB = rowB & 7;

    float accE[4][4], accO[4][4];
#pragma unroll
    for (int i = 0; i < 4; i++)
#pragma unroll
        for (int j = 0; j < 4; j++) { accE[i][j] = 0.f; accO[i][j] = 0.f; }

    // prime pipeline: stages 0 and 1
    fetch_stage(sb,       slabS[0], koffS[0], khS[0], tid);
    fetch_stage(sb + STG, slabS[1], koffS[1], khS[1], tid);

    for (int st = 0; st < nStage; st++) {
        const uint32_t S = sb + (uint32_t)(st & 1) * STG;
        if (st + 1 < nStage) { CPWAIT(1); } else { CPWAIT(0); }
        __syncthreads();

        const uint32_t W0 = S + 32768;            // kx=0
        const uint32_t W1 = S + 32768 + 16384;    // kx=1
        const uint32_t W2 = S + 32768 + 32768;    // kx=2
#pragma unroll
        for (int s = 0; s < 8; s++) {
            int ck = 2 * s + cSel;
            uint32_t offA0 = chunk_off(ck, rs0);
            uint32_t offA1 = chunk_off(ck, rs1);
            uint32_t offB  = chunk_off(ck, rsB);
            uint32_t a0[4], a1[4];
            ldsm4(a0, S + baseA0 + offA0);
            ldsm4(a1, S + baseA1 + offA1);
#pragma unroll
            for (int j2 = 0; j2 < 2; j2++) {
                uint32_t bb = (j2 ? baseB1 : baseB0) + offB;
                uint32_t b1v[4], b2v[4], b0v[4];
                ldsm4(b1v, W1 + bb);
                ldsm4(b2v, W2 + bb);
                ldsm4(b0v, W0 + bb);
                mma_tf32(accE[2 * j2],     a0, b1v[0], b1v[2]);   // even: kx=1, cell m
                mma_tf32(accE[2 * j2 + 1], a0, b1v[1], b1v[3]);
                mma_tf32(accO[2 * j2],     a0, b2v[0], b2v[2]);   // odd:  kx=2, cell m
                mma_tf32(accO[2 * j2 + 1], a0, b2v[1], b2v[3]);
                mma_tf32(accO[2 * j2],     a1, b0v[0], b0v[2]);   // odd:  kx=0, cell m+1
                mma_tf32(accO[2 * j2 + 1], a1, b0v[1], b0v[3]);
            }
        }
        __syncthreads();
        if (st + 2 < nStage)
            fetch_stage(S, slabS[st + 2], koffS[st + 2], khS[st + 2], tid);
    }

    // ---------------- epilogue: stores + stats ----------------
    const int g = lane >> 2;
    const int n0base = (lane & 3) * 2;
    const int sbase = ((b * TQ + ot) * YOQ + oy) * XOQ;
    const int mA = r0 + g;
    const int mB = r0 + g + 8;
    const bool oddBvalid = (mB != 127);          // ox=255 doesn't exist

    float sl[8], ql[8];
#pragma unroll
    for (int nt = 0; nt < 4; nt++) {
        int n0 = half * 32 + nt * 8 + n0base;
        *(float2*)(out + (size_t)(sbase + 2 * mA) * COUTQ + n0) =
            make_float2(accE[nt][0], accE[nt][1]);
        *(float2*)(out + (size_t)(sbase + 2 * mB) * COUTQ + n0) =
            make_float2(accE[nt][2], accE[nt][3]);
        *(float2*)(out + (size_t)(sbase + 2 * mA + 1) * COUTQ + n0) =
            make_float2(accO[nt][0], accO[nt][1]);
        if (oddBvalid)
            *(float2*)(out + (size_t)(sbase + 2 * mB + 1) * COUTQ + n0) =
                make_float2(accO[nt][2], accO[nt][3]);
#pragma unroll
        for (int c = 0; c < 2; c++) {
            float e0 = accE[nt][c], e2 = accE[nt][2 + c];
            float o0 = accO[nt][c], o2 = oddBvalid ? accO[nt][2 + c] : 0.f;
            sl[nt * 2 + c] = e0 + e2 + o0 + o2;
            ql[nt * 2 + c] = e0 * e0 + e2 * e2 + o0 * o0 + o2 * o2;
        }
    }
#pragma unroll
    for (int d = 4; d <= 16; d <<= 1) {
#pragma unroll
        for (int i = 0; i < 8; i++) {
            sl[i] += __shfl_xor_sync(0xffffffffu, sl[i], d);
            ql[i] += __shfl_xor_sync(0xffffffffu, ql[i], d);
        }
    }
    __syncthreads();                          // pipeline drained; reuse smem
    float* redS = (float*)smem;               // [16 warps][4][8]
    float* redQ = (float*)(smem + 16 * 4 * 8 * 4);
    if (lane < 4) {
#pragma unroll
        for (int i = 0; i < 8; i++) {
            redS[(wid * 4 + lane) * 8 + i] = sl[i];
            redQ[(wid * 4 + lane) * 8 + i] = ql[i];
        }
    }
    __syncthreads();
    if (tid < COUTQ) {
        int h2 = tid >> 5, nt = (tid >> 3) & 3, c4 = (tid >> 1) & 3, cc = tid & 1;
        int idx = nt * 2 + cc;
        float S = 0.f, Q = 0.f;
#pragma unroll
        for (int w2 = 0; w2 < 8; w2++) {
            int w = h2 * 8 + w2;
            S += redS[(w * 4 + c4) * 8 + idx];
            Q += redQ[(w * 4 + c4) * 8 + idx];
        }
        atomicAdd(&g_sum[tid], S);
        atomicAdd(&g_sumsq[tid], Q);
    }

    // ---------------- active-site mask ----------------
    bool act = false;
    if (tid < XOQ) {
        int ox2 = tid;
        int xc[2]; int nxc = 0;
        if ((ox2 & 1) == 0) { xc[nxc++] = ox2 >> 1; }
        else {
            int c0 = (ox2 + 1) >> 1;
            if (c0 < XQ) xc[nxc++] = c0;
            xc[nxc++] = (ox2 - 1) >> 1;
        }
        for (int kt = 0; kt < 3 && !act; kt++) {
            int ctv = ot + 1 - kt;
            if (ctv < 0 || ctv >= TQ) continue;
            for (int yt = 0; yt < nky && !act; yt++) {
                int cb2 = ((b * TQ + ctv) * YQ + cys[yt]) * XQ;
                for (int xi = 0; xi < nxc; xi++)
                    if (g_occ[cb2 + xc[xi]] > 0) { act = true; break; }
            }
        }
        g_mask[sbase + ox2] = act ? 1 : 0;
    }
    unsigned bal = __ballot_sync(0xffffffffu, act);
    if (lane == 0 && bal) atomicAdd(&g_nactive, __popc(bal));
}

// ---------------- K3: fold BN params ----------------
__global__ void k_bn(const float* __restrict__ gamma, const float* __restrict__ beta) {
    int c = threadIdx.x;
    if (c >= COUTQ) return;
    float n = (float)max(g_nactive, 1);
    float mean = g_sum[c] / n;
    float var  = g_sumsq[c] / n - mean * mean;
    float rstd = rsqrtf(var + EPSQ);
    float sc   = rstd * gamma[c];
    g_scale[c] = sc;
    g_shift[c] = beta[c] - mean * sc;
}

// ---------------- K4: normalize + relu + mask (in place) ----------------
__global__ void k_final(float* __restrict__ out) {
    int i = blockIdx.x * 256 + threadIdx.x;
    int site = i >> 4;
    int cg   = i & 15;
    float4 v  = ((float4*)out)[i];
    float4 sc = ((const float4*)g_scale)[cg];
    float4 sh = ((const float4*)g_shift)[cg];
    float  m  = g_mask[site] ? 1.f : 0.f;
    v.x = fmaxf(v.x * sc.x + sh.x, 0.f) * m;
    v.y = fmaxf(v.y * sc.y + sh.y, 0.f) * m;
    v.z = fmaxf(v.z * sc.z + sh.z, 0.f) * m;
    v.w = fmaxf(v.w * sc.w + sh.w, 0.f) * m;
    ((float4*)out)[i] = v;
}

// ---------------- launch ----------------
extern "C" void kernel_launch(void* const* d_in, const int* in_sizes, int n_in,
                              void* d_out, int out_size) {
    const float* feats  = (const float*)d_in[0];
    const float* weight = (const float*)d_in[1];
    const float* gamma  = (const float*)d_in[2];
    const float* beta   = (const float*)d_in[3];
    const int*   cb     = (const int*)d_in[4];
    const int*   ct     = (const int*)d_in[5];
    const int*   cy     = (const int*)d_in[6];
    const int*   cx     = (const int*)d_in[7];
    float* out = (float*)d_out;

    cudaFuncSetAttribute(k_conv, cudaFuncAttributeMaxDynamicSharedMemorySize, CONV_DYN_SMEM);

    k_zero<<<NCELL * CIN / 4 / 256, 256>>>();
    k_prepw<<<(27 * CIN * COUTQ + 255) / 256, 256>>>(weight);
    k_scatter<<<NPTS * 32 / 256, 256>>>(feats, cb, ct, cy, cx);
    k_convert<<<NCELL * CIN / 4 / 256, 256>>>();
    k_conv<<<BQ * TQ * YOQ, 512, CONV_DYN_SMEM>>>(out);
    k_bn<<<1, 64>>>(gamma, beta);
    k_final<<<NSITE * 16 / 256, 256>>>(out);
}

// round 8
// speedup vs baseline: 1.1159x; 1.1159x over previous
#include <cuda_runtime.h>
#include <cuda_bf16.h>
#include <cstdint>

// ---------------- problem constants ----------------
#define BQ 2
#define TQ 8
#define YQ 128
#define XQ 128
#define CIN 128
#define COUTQ 64
#define YOQ 255
#define XOQ 255
#define NPTS 262144
#define NCELL (BQ*TQ*YQ*XQ)
#define NSITE (BQ*TQ*YOQ*XOQ)
#define EPSQ 1e-5f

// ---------------- device scratch ----------------
__device__ __align__(16) float g_A[(size_t)NCELL * CIN];   // fp32 cell grid (tf32-rounded in place)
__device__ __align__(16) int   g_occ[NCELL];
__device__ unsigned char       g_mask[NSITE];
__device__ __align__(16) float g_sum[COUTQ];
__device__ __align__(16) float g_sumsq[COUTQ];
__device__ int                 g_nactive;
__device__ __align__(16) float g_scale[COUTQ];
__device__ __align__(16) float g_shift[COUTQ];
// tf32(fp32-bit) weights, linear [27 koff][co][ci]
__device__ __align__(16) uint32_t g_Wt32[27 * COUTQ * CIN];

// ---------------- helpers ----------------
__device__ __forceinline__ uint32_t smem_u32(const void* p) {
    uint32_t a;
    asm("{ .reg .u64 t; cvta.to.shared.u64 t, %1; cvt.u32.u64 %0, t; }" : "=r"(a) : "l"(p));
    return a;
}
__device__ __forceinline__ void ldsm4(uint32_t* r, uint32_t addr) {
    asm volatile("ldmatrix.sync.aligned.m8n8.x4.shared.b16 {%0,%1,%2,%3}, [%4];"
        : "=r"(r[0]), "=r"(r[1]), "=r"(r[2]), "=r"(r[3]) : "r"(addr));
}
__device__ __forceinline__ void mma_tf32(float* c, const uint32_t* a, uint32_t b0, uint32_t b1) {
    asm volatile("mma.sync.aligned.m16n8k8.row.col.f32.tf32.tf32.f32 "
        "{%0,%1,%2,%3}, {%4,%5,%6,%7}, {%8,%9}, {%0,%1,%2,%3};"
        : "+f"(c[0]), "+f"(c[1]), "+f"(c[2]), "+f"(c[3])
        : "r"(a[0]), "r"(a[1]), "r"(a[2]), "r"(a[3]), "r"(b0), "r"(b1));
}
__device__ __forceinline__ uint32_t f2tf32(float x) {
    uint32_t t;
    asm("cvt.rna.tf32.f32 %0, %1;" : "=r"(t) : "f"(x));
    return t;
}
#define CPASYNC16(sa, gp) \
    asm volatile("cp.async.cg.shared.global [%0], [%1], 16;" :: "r"(sa), "l"(gp))
#define CPCOMMIT() asm volatile("cp.async.commit_group;" ::: "memory")
#define CPWAIT(n)  asm volatile("cp.async.wait_group %0;" :: "n"(n) : "memory")

// 256B rows of 16 16B-chunks, XOR-swizzled within 8-chunk groups.
__device__ __forceinline__ uint32_t chunk_off(int c16, int rs) {
    return (uint32_t)(((c16 & 8) << 4) | (((c16 & 7) ^ rs) << 4));
}

// ---------------- K0: zero scratch ----------------
__global__ void k_zero() {
    int idx = blockIdx.x * 256 + threadIdx.x;
    if (idx < NCELL * CIN / 4)
        ((float4*)g_A)[idx] = make_float4(0.f, 0.f, 0.f, 0.f);
    if (idx < NCELL / 4)
        ((int4*)g_occ)[idx] = make_int4(0, 0, 0, 0);
    if (idx < COUTQ) { g_sum[idx] = 0.f; g_sumsq[idx] = 0.f; }
    if (idx == 0) g_nactive = 0;
}

// ---------------- K0b: tf32-round + transpose weights -> [koff][co][ci] ----------------
__global__ void k_prepw(const float* __restrict__ W) {
    int i = blockIdx.x * 256 + threadIdx.x;
    if (i >= 27 * CIN * COUTQ) return;
    int koff = i / (CIN * COUTQ);
    int r    = i % (CIN * COUTQ);
    int ci = r / COUTQ, co = r % COUTQ;
    g_Wt32[(size_t)koff * 8192 + co * CIN + ci] = f2tf32(W[i]);
}

// ---------------- K1: scatter points ----------------
__global__ void k_scatter(const float* __restrict__ feats,
                          const int* __restrict__ cb, const int* __restrict__ ct,
                          const int* __restrict__ cy, const int* __restrict__ cx) {
    int i = blockIdx.x * 256 + threadIdx.x;
    if (i >= NPTS * 32) return;
    int p  = i >> 5;
    int c4 = i & 31;
    int cell = ((cb[p] * TQ + ct[p]) * YQ + cy[p]) * XQ + cx[p];
    float4 v = ((const float4*)feats)[p * 32 + c4];
    float* dst = &g_A[(size_t)cell * CIN + c4 * 4];
    atomicAdd(dst + 0, v.x);
    atomicAdd(dst + 1, v.y);
    atomicAdd(dst + 2, v.z);
    atomicAdd(dst + 3, v.w);
    if (c4 == 0) atomicAdd(&g_occ[cell], 1);
}

// ---------------- K1b: tf32-round g_A in place ----------------
__global__ void k_convert() {
    int i = blockIdx.x * 256 + threadIdx.x;
    float4 v = ((const float4*)g_A)[i];
    v.x = __uint_as_float(f2tf32(v.x));
    v.y = __uint_as_float(f2tf32(v.y));
    v.z = __uint_as_float(f2tf32(v.z));
    v.w = __uint_as_float(f2tf32(v.w));
    ((float4*)g_A)[i] = v;
}

// ---------------- K2: row-paired, K-split stage-pipelined tf32 conv ----------------
// CTA = (bt, slot): rows oy0=slot, oy1=slot+128 (slot 127: row0 only).
// Stage (112KB): A-row0-half [0,32K), A-row1-half [32K,64K),
//                W-half at 65536 + kx*16384 (64 co x 256B, swizzled)
// 2 stages double-buffered, depth-2 pipeline.
#define STG 114688
#define CONV_DYN_SMEM (2 * STG)

__device__ __forceinline__ void fetch_stage(uint32_t dst, int slab0, int slab1,
                                            int koff, int kh, int tid) {
    const char* gA0 = (const char*)g_A + (size_t)slab0 * 65536 + kh * 256;
    const char* gA1 = (const char*)g_A + (size_t)slab1 * 65536 + kh * 256;
#pragma unroll
    for (int j = 0; j < 4; j++) {
        int e = tid + j * 512;
        int cell = e >> 4, c16 = e & 15;
        uint32_t o = cell * 256 + chunk_off(c16, cell & 7);
        const size_t so = (size_t)cell * 512 + c16 * 16;
        CPASYNC16(dst + o,         gA0 + so);
        CPASYNC16(dst + 32768 + o, gA1 + so);
    }
    const char* gW = (const char*)g_Wt32 + (size_t)koff * 32768 + kh * 256;
#pragma unroll
    for (int j = 0; j < 6; j++) {
        int e = tid + j * 512;
        int kx = e >> 10, w = e & 1023;
        int co = w >> 4, c16 = w & 15;
        CPASYNC16(dst + 65536 + kx * 16384 + co * 256 + chunk_off(c16, co & 7),
                  gW + (size_t)kx * 32768 + (size_t)co * 512 + c16 * 16);
    }
    CPCOMMIT();
}

__global__ void __launch_bounds__(512, 1) k_conv(float* __restrict__ out) {
    extern __shared__ char smem[];
    const uint32_t sb = smem_u32(smem);
    const int tid = threadIdx.x, wid = tid >> 5, lane = tid & 31;
    const int half = wid >> 3, wm = wid & 7;

    const int slot = blockIdx.x & 127;
    const int bt   = blockIdx.x >> 7;
    const int b = bt >> 3, ot = bt & 7;
    const int oy0 = slot;
    const bool valid1 = (slot < 127);
    const int oy1 = valid1 ? slot + 128 : slot;

    // y taps (same parity for both rows)
    int nky, cys[2], kys[2];
    if ((oy0 & 1) == 0) { nky = 1; cys[0] = oy0 >> 1;       kys[0] = 1; }
    else                { nky = 2; cys[0] = (oy0 + 1) >> 1; kys[0] = 0;
                                   cys[1] = (oy0 - 1) >> 1; kys[1] = 2; }
    const int dy1 = valid1 ? 64 : 0;       // cy offset for row1

    // stage list (iter x 2 K-halves)
    int nStage = 0;
    int slab0S[12], slab1S[12], koffS[12], khS[12];
    for (int kt = 0; kt < 3; kt++) {
        int ctv = ot + 1 - kt;
        if (ctv < 0 || ctv >= TQ) continue;
        for (int yt = 0; yt < nky; yt++) {
            int base = (b * TQ + ctv) * YQ + cys[yt];
            int koff = (kt * 3 + kys[yt]) * 3;
            for (int kh = 0; kh < 2; kh++) {
                slab0S[nStage] = base;
                slab1S[nStage] = base + dy1;
                koffS[nStage] = koff; khS[nStage] = kh;
                nStage++;
            }
        }
    }

    // ldmatrix geometry (256B rows)
    const int r0 = wm << 4;
    const int matL = lane >> 3, rr = lane & 7;
    const int rA0 = r0 + rr + ((matL & 1) << 3);
    const int rA1 = rA0 + 1;                 // cell m+1 (row 128 -> garbage, masked)
    const int cSel = matL >> 1;
    const uint32_t baseA0 = (uint32_t)rA0 * 256; const int rs0 = rA0 & 7;
    const uint32_t baseA1 = (uint32_t)rA1 * 256; const int rs1 = rA1 & 7;
    const int rowB = half * 32 + rr + ((matL & 1) << 3);
    const uint32_t baseB0 = (uint32_t)rowB * 256;
    const uint32_t baseB1 = baseB0 + 16 * 256;
    const int rsB = rowB & 7;

    float accE[2][4][4], accO[2][4][4];
#pragma unroll
    for (int r = 0; r < 2; r++)
#pragma unroll
        for (int i = 0; i < 4; i++)
#pragma unroll
            for (int j = 0; j < 4; j++) { accE[r][i][j] = 0.f; accO[r][i][j] = 0.f; }

    // prime pipeline
    fetch_stage(sb,       slab0S[0], slab1S[0], koffS[0], khS[0], tid);
    fetch_stage(sb + STG, slab0S[1], slab1S[1], koffS[1], khS[1], tid);

    for (int st = 0; st < nStage; st++) {
        const uint32_t S = sb + (uint32_t)(st & 1) * STG;
        if (st + 1 < nStage) { CPWAIT(1); } else { CPWAIT(0); }
        __syncthreads();

        const uint32_t W0 = S + 65536;            // kx=0
        const uint32_t W1 = S + 65536 + 16384;    // kx=1
        const uint32_t W2 = S + 65536 + 32768;    // kx=2
#pragma unroll
        for (int s = 0; s < 8; s++) {
            int ck = 2 * s + cSel;
            uint32_t offA0 = chunk_off(ck, rs0);
            uint32_t offA1 = chunk_off(ck, rs1);
            uint32_t offB  = chunk_off(ck, rsB);
            uint32_t a0r0[4], a1r0[4], a0r1[4], a1r1[4];
            ldsm4(a0r0, S + baseA0 + offA0);
            ldsm4(a1r0, S + baseA1 + offA1);
            ldsm4(a0r1, S + 32768 + baseA0 + offA0);
            ldsm4(a1r1, S + 32768 + baseA1 + offA1);
#pragma unroll
            for (int j2 = 0; j2 < 2; j2++) {
                uint32_t bb = (j2 ? baseB1 : baseB0) + offB;
                uint32_t b1v[4], b2v[4], b0v[4];
                ldsm4(b1v, W1 + bb);
                ldsm4(b2v, W2 + bb);
                ldsm4(b0v, W0 + bb);
                mma_tf32(accE[0][2 * j2],     a0r0, b1v[0], b1v[2]);
                mma_tf32(accE[0][2 * j2 + 1], a0r0, b1v[1], b1v[3]);
                mma_tf32(accO[0][2 * j2],     a0r0, b2v[0], b2v[2]);
                mma_tf32(accO[0][2 * j2 + 1], a0r0, b2v[1], b2v[3]);
                mma_tf32(accO[0][2 * j2],     a1r0, b0v[0], b0v[2]);
                mma_tf32(accO[0][2 * j2 + 1], a1r0, b0v[1], b0v[3]);
                mma_tf32(accE[1][2 * j2],     a0r1, b1v[0], b1v[2]);
                mma_tf32(accE[1][2 * j2 + 1], a0r1, b1v[1], b1v[3]);
                mma_tf32(accO[1][2 * j2],     a0r1, b2v[0], b2v[2]);
                mma_tf32(accO[1][2 * j2 + 1], a0r1, b2v[1], b2v[3]);
                mma_tf32(accO[1][2 * j2],     a1r1, b0v[0], b0v[2]);
                mma_tf32(accO[1][2 * j2 + 1], a1r1, b0v[1], b0v[3]);
            }
        }
        __syncthreads();
        if (st + 2 < nStage)
            fetch_stage(S, slab0S[st + 2], slab1S[st + 2], koffS[st + 2], khS[st + 2], tid);
    }

    // ---------------- epilogue: stores + stats ----------------
    const int g = lane >> 2;
    const int n0base = (lane & 3) * 2;
    const int mA = r0 + g;
    const int mB = r0 + g + 8;
    const bool oddBvalid = (mB != 127);          // ox=255 doesn't exist
    const int sb0 = ((b * TQ + ot) * YOQ + oy0) * XOQ;
    const int sb1 = ((b * TQ + ot) * YOQ + oy1) * XOQ;

    float sl[8] = {0,0,0,0,0,0,0,0}, ql[8] = {0,0,0,0,0,0,0,0};
#pragma unroll
    for (int r = 0; r < 2; r++) {
        if (r == 1 && !valid1) break;
        int sbase = r ? sb1 : sb0;
#pragma unroll
        for (int nt = 0; nt < 4; nt++) {
            int n0 = half * 32 + nt * 8 + n0base;
            *(float2*)(out + (size_t)(sbase + 2 * mA) * COUTQ + n0) =
                make_float2(accE[r][nt][0], accE[r][nt][1]);
            *(float2*)(out + (size_t)(sbase + 2 * mB) * COUTQ + n0) =
                make_float2(accE[r][nt][2], accE[r][nt][3]);
            *(float2*)(out + (size_t)(sbase + 2 * mA + 1) * COUTQ + n0) =
                make_float2(accO[r][nt][0], accO[r][nt][1]);
            if (oddBvalid)
                *(float2*)(out + (size_t)(sbase + 2 * mB + 1) * COUTQ + n0) =
                    make_float2(accO[r][nt][2], accO[r][nt][3]);
#pragma unroll
            for (int c = 0; c < 2; c++) {
                float e0 = accE[r][nt][c], e2 = accE[r][nt][2 + c];
                float o0 = accO[r][nt][c], o2 = oddBvalid ? accO[r][nt][2 + c] : 0.f;
                sl[nt * 2 + c] += e0 + e2 + o0 + o2;
                ql[nt * 2 + c] += e0 * e0 + e2 * e2 + o0 * o0 + o2 * o2;
            }
        }
    }
#pragma unroll
    for (int d = 4; d <= 16; d <<= 1) {
#pragma unroll
        for (int i = 0; i < 8; i++) {
            sl[i] += __shfl_xor_sync(0xffffffffu, sl[i], d);
            ql[i] += __shfl_xor_sync(0xffffffffu, ql[i], d);
        }
    }
    __syncthreads();                          // pipeline drained; reuse smem
    float* redS = (float*)smem;               // [16 warps][4][8]
    float* redQ = (float*)(smem + 16 * 4 * 8 * 4);
    if (lane < 4) {
#pragma unroll
        for (int i = 0; i < 8; i++) {
            redS[(wid * 4 + lane) * 8 + i] = sl[i];
            redQ[(wid * 4 + lane) * 8 + i] = ql[i];
        }
    }
    __syncthreads();
    if (tid < COUTQ) {
        int h2 = tid >> 5, nt = (tid >> 3) & 3, c4 = (tid >> 1) & 3, cc = tid & 1;
        int idx = nt * 2 + cc;
        float S = 0.f, Q = 0.f;
#pragma unroll
        for (int w2 = 0; w2 < 8; w2++) {
            int w = h2 * 8 + w2;
            S += redS[(w * 4 + c4) * 8 + idx];
            Q += redQ[(w * 4 + c4) * 8 + idx];
        }
        atomicAdd(&g_sum[tid], S);
        atomicAdd(&g_sumsq[tid], Q);
    }

    // ---------------- active-site mask (row0: tid<255, row1: tid-256<255) ----------------
    bool act = false;
    int rsel = tid >> 8;                      // 0 or 1
    int ox2  = tid & 255;
    bool doMask = (ox2 < XOQ) && (rsel == 0 || valid1);
    if (doMask) {
        int xc[2]; int nxc = 0;
        if ((ox2 & 1) == 0) { xc[nxc++] = ox2 >> 1; }
        else {
            int c0 = (ox2 + 1) >> 1;
            if (c0 < XQ) xc[nxc++] = c0;
            xc[nxc++] = (ox2 - 1) >> 1;
        }
        int dy = rsel ? dy1 : 0;
        for (int kt = 0; kt < 3 && !act; kt++) {
            int ctv = ot + 1 - kt;
            if (ctv < 0 || ctv >= TQ) continue;
            for (int yt = 0; yt < nky && !act; yt++) {
                int cb2 = ((b * TQ + ctv) * YQ + cys[yt] + dy) * XQ;
                for (int xi = 0; xi < nxc; xi++)
                    if (g_occ[cb2 + xc[xi]] > 0) { act = true; break; }
            }
        }
        g_mask[(rsel ? sb1 : sb0) + ox2] = act ? 1 : 0;
    }
    unsigned bal = __ballot_sync(0xffffffffu, act);
    if (lane == 0 && bal) atomicAdd(&g_nactive, __popc(bal));
}

// ---------------- K3: fold BN params ----------------
__global__ void k_bn(const float* __restrict__ gamma, const float* __restrict__ beta) {
    int c = threadIdx.x;
    if (c >= COUTQ) return;
    float n = (float)max(g_nactive, 1);
    float mean = g_sum[c] / n;
    float var  = g_sumsq[c] / n - mean * mean;
    float rstd = rsqrtf(var + EPSQ);
    float sc   = rstd * gamma[c];
    g_scale[c] = sc;
    g_shift[c] = beta[c] - mean * sc;
}

// ---------------- K4: normalize + relu + mask (in place) ----------------
__global__ void k_final(float* __restrict__ out) {
    int i = blockIdx.x * 256 + threadIdx.x;
    int site = i >> 4;
    int cg   = i & 15;
    float4 v  = ((float4*)out)[i];
    float4 sc = ((const float4*)g_scale)[cg];
    float4 sh = ((const float4*)g_shift)[cg];
    float  m  = g_mask[site] ? 1.f : 0.f;
    v.x = fmaxf(v.x * sc.x + sh.x, 0.f) * m;
    v.y = fmaxf(v.y * sc.y + sh.y, 0.f) * m;
    v.z = fmaxf(v.z * sc.z + sh.z, 0.f) * m;
    v.w = fmaxf(v.w * sc.w + sh.w, 0.f) * m;
    ((float4*)out)[i] = v;
}

// ---------------- launch ----------------
extern "C" void kernel_launch(void* const* d_in, const int* in_sizes, int n_in,
                              void* d_out, int out_size) {
    const float* feats  = (const float*)d_in[0];
    const float* weight = (const float*)d_in[1];
    const float* gamma  = (const float*)d_in[2];
    const float* beta   = (const float*)d_in[3];
    const int*   cb     = (const int*)d_in[4];
    const int*   ct     = (const int*)d_in[5];
    const int*   cy     = (const int*)d_in[6];
    const int*   cx     = (const int*)d_in[7];
    float* out = (float*)d_out;

    cudaFuncSetAttribute(k_conv, cudaFuncAttributeMaxDynamicSharedMemorySize, CONV_DYN_SMEM);

    k_zero<<<NCELL * CIN / 4 / 256, 256>>>();
    k_prepw<<<(27 * CIN * COUTQ + 255) / 256, 256>>>(weight);
    k_scatter<<<NPTS * 32 / 256, 256>>>(feats, cb, ct, cy, cx);
    k_convert<<<NCELL * CIN / 4 / 256, 256>>>();
    k_conv<<<16 * 128, 512, CONV_DYN_SMEM>>>(out);
    k_bn<<<1, 64>>>(gamma, beta);
    k_final<<<NSITE * 16 / 256, 256>>>(out);
}

// round 9
// speedup vs baseline: 1.1738x; 1.0519x over previous
#include <cuda_runtime.h>
#include <cuda_bf16.h>
#include <cstdint>

// ---------------- problem constants ----------------
#define BQ 2
#define TQ 8
#define YQ 128
#define XQ 128
#define CIN 128
#define COUTQ 64
#define YOQ 255
#define XOQ 255
#define NPTS 262144
#define NCELL (BQ*TQ*YQ*XQ)
#define NSITE (BQ*TQ*YOQ*XOQ)
#define NSLAB (BQ*TQ*YQ)
#define EPSQ 1e-5f

// ---------------- device scratch ----------------
__device__ __align__(16) float g_A[(size_t)NCELL * CIN];   // fp32 cell grid
// pre-swizzled tf32 A images: [slab][kh][cell*256 + chunk_off] (32KB per half)
__device__ __align__(16) unsigned char g_Ab[(size_t)NSLAB * 65536];
__device__ __align__(16) int   g_occ[NCELL];
__device__ unsigned char       g_mask[NSITE];
__device__ __align__(16) float g_sum[COUTQ];
__device__ __align__(16) float g_sumsq[COUTQ];
__device__ int                 g_nactive;
__device__ __align__(16) float g_scale[COUTQ];
__device__ __align__(16) float g_shift[COUTQ];
// pre-swizzled tf32 W images: [ktky 0..8][kh][kx][co*256 + chunk_off] (48KB per (ktky,kh))
__device__ __align__(16) unsigned char g_Wt[9 * 2 * 49152];

// ---------------- helpers ----------------
__device__ __forceinline__ uint32_t smem_u32(const void* p) {
    uint32_t a;
    asm("{ .reg .u64 t; cvta.to.shared.u64 t, %1; cvt.u32.u64 %0, t; }" : "=r"(a) : "l"(p));
    return a;
}
__device__ __forceinline__ void ldsm4(uint32_t* r, uint32_t addr) {
    asm volatile("ldmatrix.sync.aligned.m8n8.x4.shared.b16 {%0,%1,%2,%3}, [%4];"
        : "=r"(r[0]), "=r"(r[1]), "=r"(r[2]), "=r"(r[3]) : "r"(addr));
}
__device__ __forceinline__ void mma_tf32(float* c, const uint32_t* a, uint32_t b0, uint32_t b1) {
    asm volatile("mma.sync.aligned.m16n8k8.row.col.f32.tf32.tf32.f32 "
        "{%0,%1,%2,%3}, {%4,%5,%6,%7}, {%8,%9}, {%0,%1,%2,%3};"
        : "+f"(c[0]), "+f"(c[1]), "+f"(c[2]), "+f"(c[3])
        : "r"(a[0]), "r"(a[1]), "r"(a[2]), "r"(a[3]), "r"(b0), "r"(b1));
}
__device__ __forceinline__ uint32_t f2tf32(float x) {
    uint32_t t;
    asm("cvt.rna.tf32.f32 %0, %1;" : "=r"(t) : "f"(x));
    return t;
}
__device__ __forceinline__ void bulkcp(uint32_t dst, const void* src, uint32_t bytes, uint32_t mbar) {
    asm volatile("cp.async.bulk.shared::cluster.global.mbarrier::complete_tx::bytes "
                 "[%0], [%1], %2, [%3];"
                 :: "r"(dst), "l"(src), "r"(bytes), "r"(mbar) : "memory");
}
#define MBARRIER_INIT(addr, cnt) \
    asm volatile("mbarrier.init.shared.b64 [%0], %1;" :: "r"((uint32_t)(addr)), "r"((uint32_t)(cnt)) : "memory")
#define MBARRIER_EXPECT_TX(addr, tx) \
    asm volatile("mbarrier.arrive.expect_tx.shared.b64 _, [%0], %1;" \
        :: "r"((uint32_t)(addr)), "r"((uint32_t)(tx)) : "memory")
#define MBARRIER_WAIT_PARITY(addr, par) do { \
    uint32_t _m = (uint32_t)(addr); uint32_t _p = (uint32_t)(par); uint32_t _d; \
    asm volatile("{\n\t.reg .pred p;\n\tmbarrier.try_wait.parity.acquire.cta.shared::cta.b64 p, [%1], %2;\n\tselp.b32 %0, 1, 0, p;\n\t}" \
        : "=r"(_d) : "r"(_m), "r"(_p) : "memory"); \
    if (!_d) { \
        asm volatile("{\n\t.reg .pred P1;\n\tWL_%=:\n\tmbarrier.try_wait.parity.acquire.cta.shared::cta.b64 P1, [%0], %1, 0x989680;\n\t@P1 bra.uni WD_%=;\n\tbra.uni WL_%=;\n\tWD_%=:\n\t}" \
            :: "r"(_m), "r"(_p) : "memory"); \
    } } while (0)

// 256B rows of 16 16B-chunks, XOR-swizzled within 8-chunk groups.
__device__ __forceinline__ uint32_t chunk_off(int c16, int rs) {
    return (uint32_t)(((c16 & 8) << 4) | (((c16 & 7) ^ rs) << 4));
}

// ---------------- K0: zero scratch ----------------
__global__ void k_zero() {
    int idx = blockIdx.x * 256 + threadIdx.x;
    if (idx < NCELL * CIN / 4)
        ((float4*)g_A)[idx] = make_float4(0.f, 0.f, 0.f, 0.f);
    if (idx < NCELL / 4)
        ((int4*)g_occ)[idx] = make_int4(0, 0, 0, 0);
    if (idx < COUTQ) { g_sum[idx] = 0.f; g_sumsq[idx] = 0.f; }
    if (idx == 0) g_nactive = 0;
}

// ---------------- K0b: tf32 + swizzled W images ----------------
// src W[koff][ci][co], koff = ktky*3+kx. dst: [ktky][kh][kx][co*256 + chunk_off(c16)]
__global__ void k_prepw(const float* __restrict__ W) {
    int i = blockIdx.x * 256 + threadIdx.x;        // 27*64*32 = 55296 chunks
    if (i >= 27 * COUTQ * 32) return;
    int koff = i >> 11;
    int r    = i & 2047;           // co*32 + c16g
    int co = r >> 5, c16g = r & 31;
    int kh = c16g >> 4, c16 = c16g & 15;
    int ktky = koff / 3, kx = koff % 3;
    uint32_t v[4];
#pragma unroll
    for (int j = 0; j < 4; j++) {
        int ci = c16g * 4 + j;
        v[j] = f2tf32(W[((size_t)koff * CIN + ci) * COUTQ + co]);
    }
    uint32_t dst = (uint32_t)(((ktky * 2 + kh) * 3 + kx) * 16384)
                 + (uint32_t)(co * 256) + chunk_off(c16, co & 7);
    *(uint4*)(g_Wt + dst) = make_uint4(v[0], v[1], v[2], v[3]);
}

// ---------------- K1: scatter points ----------------
__global__ void k_scatter(const float* __restrict__ feats,
                          const int* __restrict__ cb, const int* __restrict__ ct,
                          const int* __restrict__ cy, const int* __restrict__ cx) {
    int i = blockIdx.x * 256 + threadIdx.x;
    if (i >= NPTS * 32) return;
    int p  = i >> 5;
    int c4 = i & 31;
    int cell = ((cb[p] * TQ + ct[p]) * YQ + cy[p]) * XQ + cx[p];
    float4 v = ((const float4*)feats)[p * 32 + c4];
    float* dst = &g_A[(size_t)cell * CIN + c4 * 4];
    atomicAdd(dst + 0, v.x);
    atomicAdd(dst + 1, v.y);
    atomicAdd(dst + 2, v.z);
    atomicAdd(dst + 3, v.w);
    if (c4 == 0) atomicAdd(&g_occ[cell], 1);
}

// ---------------- K1b: tf32 + swizzled A images ----------------
__global__ void k_convert() {
    int i = blockIdx.x * 256 + threadIdx.x;        // NCELL*CIN/4 chunks
    int slab = i >> 12;
    int r    = i & 4095;           // kh*2048 + cell*16 + c16
    int kh = r >> 11, r2 = r & 2047;
    int cell = r2 >> 4, c16 = r2 & 15;
    const float4 v = *(const float4*)(g_A + (((size_t)slab * 128 + cell) * CIN + kh * 64 + c16 * 4));
    uint4 o = make_uint4(f2tf32(v.x), f2tf32(v.y), f2tf32(v.z), f2tf32(v.w));
    uint32_t dst = (uint32_t)(kh * 32768) + (uint32_t)(cell * 256) + chunk_off(c16, cell & 7);
    *(uint4*)(g_Ab + (size_t)slab * 65536 + dst) = o;
}

// ---------------- K2: row-paired, bulk-copy stage-pipelined tf32 conv ----------------
// CTA = (bt, slot): rows oy0=slot, oy1=slot+128.
// Stage (112KB): A-row0 [0,32K), A-row1 [32K,64K), W [64K,112K) (kx stride 16K)
#define STG 114688
#define CONV_DYN_SMEM (2 * STG)

__global__ void __launch_bounds__(512, 1) k_conv(float* __restrict__ out) {
    extern __shared__ char smem[];
    __shared__ __align__(8) uint64_t mb[2];
    const uint32_t sb = smem_u32(smem);
    const uint32_t mb0 = smem_u32(&mb[0]), mb1 = smem_u32(&mb[1]);
    const int tid = threadIdx.x, wid = tid >> 5, lane = tid & 31;
    const int half = wid >> 3, wm = wid & 7;

    const int slot = blockIdx.x & 127;
    const int bt   = blockIdx.x >> 7;
    const int b = bt >> 3, ot = bt & 7;
    const int oy0 = slot;
    const bool valid1 = (slot < 127);
    const int oy1 = valid1 ? slot + 128 : slot;

    // y taps (same parity for both rows)
    int nky, cys[2], kys[2];
    if ((oy0 & 1) == 0) { nky = 1; cys[0] = oy0 >> 1;       kys[0] = 1; }
    else                { nky = 2; cys[0] = (oy0 + 1) >> 1; kys[0] = 0;
                                   cys[1] = (oy0 - 1) >> 1; kys[1] = 2; }
    const int dy1 = valid1 ? 64 : 0;

    // stage list (iter x 2 K-halves)
    int nStage = 0;
    int slab0S[12], slab1S[12], wimgS[12];
    for (int kt = 0; kt < 3; kt++) {
        int ctv = ot + 1 - kt;
        if (ctv < 0 || ctv >= TQ) continue;
        for (int yt = 0; yt < nky; yt++) {
            int base = (b * TQ + ctv) * YQ + cys[yt];
            int ktky = kt * 3 + kys[yt];
            for (int kh = 0; kh < 2; kh++) {
                slab0S[nStage] = base;
                slab1S[nStage] = base + dy1;
                wimgS[nStage]  = (ktky * 2 + kh);
                nStage++;
            }
        }
    }
    // encode kh into slab image offset: kh = stage parity (kh alternates 0,1)
    // (slab image half offset handled in fetch below via stage index parity)

    if (tid == 0) { MBARRIER_INIT(mb0, 1); MBARRIER_INIT(mb1, 1); }
    __syncthreads();

    // ldmatrix geometry
    const int r0 = wm << 4;
    const int matL = lane >> 3, rr = lane & 7;
    const int rA0 = r0 + rr + ((matL & 1) << 3);
    const int rA1 = rA0 + 1;                 // cell m+1 (row 128 -> garbage, masked)
    const int cSel = matL >> 1;
    const uint32_t baseA0 = (uint32_t)rA0 * 256; const int rs0 = rA0 & 7;
    const uint32_t baseA1 = (uint32_t)rA1 * 256; const int rs1 = rA1 & 7;
    const int rowB = half * 32 + rr + ((matL & 1) << 3);
    const uint32_t baseB0 = (uint32_t)rowB * 256;
    const uint32_t baseB1 = baseB0 + 16 * 256;
    const int rsB = rowB & 7;

    float accE[2][4][4], accO[2][4][4];
#pragma unroll
    for (int r = 0; r < 2; r++)
#pragma unroll
        for (int i = 0; i < 4; i++)
#pragma unroll
            for (int j = 0; j < 4; j++) { accE[r][i][j] = 0.f; accO[r][i][j] = 0.f; }

#define FETCH(ST, DST, MBAR) do { \
    int _kh = (ST) & 1; \
    MBARRIER_EXPECT_TX(MBAR, STG); \
    bulkcp((DST),         g_Ab + (size_t)slab0S[ST] * 65536 + _kh * 32768, 32768, MBAR); \
    bulkcp((DST) + 32768, g_Ab + (size_t)slab1S[ST] * 65536 + _kh * 32768, 32768, MBAR); \
    bulkcp((DST) + 65536, g_Wt + (size_t)wimgS[ST] * 49152, 49152, MBAR); \
} while (0)

    if (tid == 0) {
        FETCH(0, sb, mb0);
        FETCH(1, sb + STG, mb1);
    }

    int ph0 = 0, ph1 = 0;
    for (int st = 0; st < nStage; st++) {
        const int buf = st & 1;
        const uint32_t S = sb + (uint32_t)buf * STG;
        if (buf) { MBARRIER_WAIT_PARITY(mb1, ph1); ph1 ^= 1; }
        else     { MBARRIER_WAIT_PARITY(mb0, ph0); ph0 ^= 1; }

        const uint32_t W0 = S + 65536;            // kx=0
        const uint32_t W1 = S + 65536 + 16384;    // kx=1
        const uint32_t W2 = S + 65536 + 32768;    // kx=2
#pragma unroll
        for (int s = 0; s < 8; s++) {
            int ck = 2 * s + cSel;
            uint32_t offA0 = chunk_off(ck, rs0);
            uint32_t offA1 = chunk_off(ck, rs1);
            uint32_t offB  = chunk_off(ck, rsB);
            uint32_t a0r0[4], a1r0[4], a0r1[4], a1r1[4];
            ldsm4(a0r0, S + baseA0 + offA0);
            ldsm4(a1r0, S + baseA1 + offA1);
            ldsm4(a0r1, S + 32768 + baseA0 + offA0);
            ldsm4(a1r1, S + 32768 + baseA1 + offA1);
#pragma unroll
            for (int j2 = 0; j2 < 2; j2++) {
                uint32_t bb = (j2 ? baseB1 : baseB0) + offB;
                uint32_t b1v[4], b2v[4], b0v[4];
                ldsm4(b1v, W1 + bb);
                ldsm4(b2v, W2 + bb);
                ldsm4(b0v, W0 + bb);
                mma_tf32(accE[0][2 * j2],     a0r0, b1v[0], b1v[2]);
                mma_tf32(accE[0][2 * j2 + 1], a0r0, b1v[1], b1v[3]);
                mma_tf32(accO[0][2 * j2],     a0r0, b2v[0], b2v[2]);
                mma_tf32(accO[0][2 * j2 + 1], a0r0, b2v[1], b2v[3]);
                mma_tf32(accO[0][2 * j2],     a1r0, b0v[0], b0v[2]);
                mma_tf32(accO[0][2 * j2 + 1], a1r0, b0v[1], b0v[3]);
                mma_tf32(accE[1][2 * j2],     a0r1, b1v[0], b1v[2]);
                mma_tf32(accE[1][2 * j2 + 1], a0r1, b1v[1], b1v[3]);
                mma_tf32(accO[1][2 * j2],     a0r1, b2v[0], b2v[2]);
                mma_tf32(accO[1][2 * j2 + 1], a0r1, b2v[1], b2v[3]);
                mma_tf32(accO[1][2 * j2],     a1r1, b0v[0], b0v[2]);
                mma_tf32(accO[1][2 * j2 + 1], a1r1, b0v[1], b0v[3]);
            }
        }
        __syncthreads();                      // all readers done with this buffer
        if (st + 2 < nStage && tid == 0)
            FETCH(st + 2, S, buf ? mb1 : mb0);
    }
#undef FETCH

    // ---------------- epilogue: stores + stats ----------------
    const int g = lane >> 2;
    const int n0base = (lane & 3) * 2;
    const int mA = r0 + g;
    const int mB = r0 + g + 8;
    const bool oddBvalid = (mB != 127);          // ox=255 doesn't exist
    const int sb0 = ((b * TQ + ot) * YOQ + oy0) * XOQ;
    const int sb1 = ((b * TQ + ot) * YOQ + oy1) * XOQ;

    float sl[8] = {0,0,0,0,0,0,0,0}, ql[8] = {0,0,0,0,0,0,0,0};
#pragma unroll
    for (int r = 0; r < 2; r++) {
        if (r == 1 && !valid1) break;
        int sbase = r ? sb1 : sb0;
#pragma unroll
        for (int nt = 0; nt < 4; nt++) {
            int n0 = half * 32 + nt * 8 + n0base;
            *(float2*)(out + (size_t)(sbase + 2 * mA) * COUTQ + n0) =
                make_float2(accE[r][nt][0], accE[r][nt][1]);
            *(float2*)(out + (size_t)(sbase + 2 * mB) * COUTQ + n0) =
                make_float2(accE[r][nt][2], accE[r][nt][3]);
            *(float2*)(out + (size_t)(sbase + 2 * mA + 1) * COUTQ + n0) =
                make_float2(accO[r][nt][0], accO[r][nt][1]);
            if (oddBvalid)
                *(float2*)(out + (size_t)(sbase + 2 * mB + 1) * COUTQ + n0) =
                    make_float2(accO[r][nt][2], accO[r][nt][3]);
#pragma unroll
            for (int c = 0; c < 2; c++) {
                float e0 = accE[r][nt][c], e2 = accE[r][nt][2 + c];
                float o0 = accO[r][nt][c], o2 = oddBvalid ? accO[r][nt][2 + c] : 0.f;
                sl[nt * 2 + c] += e0 + e2 + o0 + o2;
                ql[nt * 2 + c] += e0 * e0 + e2 * e2 + o0 * o0 + o2 * o2;
            }
        }
    }
#pragma unroll
    for (int d = 4; d <= 16; d <<= 1) {
#pragma unroll
        for (int i = 0; i < 8; i++) {
            sl[i] += __shfl_xor_sync(0xffffffffu, sl[i], d);
            ql[i] += __shfl_xor_sync(0xffffffffu, ql[i], d);
        }
    }
    __syncthreads();                          // pipeline drained; reuse smem
    float* redS = (float*)smem;               // [16 warps][4][8]
    float* redQ = (float*)(smem + 16 * 4 * 8 * 4);
    if (lane < 4) {
#pragma unroll
        for (int i = 0; i < 8; i++) {
            redS[(wid * 4 + lane) * 8 + i] = sl[i];
            redQ[(wid * 4 + lane) * 8 + i] = ql[i];
        }
    }
    __syncthreads();
    if (tid < COUTQ) {
        int h2 = tid >> 5, nt = (tid >> 3) & 3, c4 = (tid >> 1) & 3, cc = tid & 1;
        int idx = nt * 2 + cc;
        float S = 0.f, Q = 0.f;
#pragma unroll
        for (int w2 = 0; w2 < 8; w2++) {
            int w = h2 * 8 + w2;
            S += redS[(w * 4 + c4) * 8 + idx];
            Q += redQ[(w * 4 + c4) * 8 + idx];
        }
        atomicAdd(&g_sum[tid], S);
        atomicAdd(&g_sumsq[tid], Q);
    }

    // ---------------- active-site mask ----------------
    bool act = false;
    int rsel = tid >> 8;
    int ox2  = tid & 255;
    bool doMask = (ox2 < XOQ) && (rsel == 0 || valid1);
    if (doMask) {
        int xc[2]; int nxc = 0;
        if ((ox2 & 1) == 0) { xc[nxc++] = ox2 >> 1; }
        else {
            int c0 = (ox2 + 1) >> 1;
            if (c0 < XQ) xc[nxc++] = c0;
            xc[nxc++] = (ox2 - 1) >> 1;
        }
        int dy = rsel ? dy1 : 0;
        for (int kt = 0; kt < 3 && !act; kt++) {
            int ctv = ot + 1 - kt;
            if (ctv < 0 || ctv >= TQ) continue;
            for (int yt = 0; yt < nky && !act; yt++) {
                int cb2 = ((b * TQ + ctv) * YQ + cys[yt] + dy) * XQ;
                for (int xi = 0; xi < nxc; xi++)
                    if (g_occ[cb2 + xc[xi]] > 0) { act = true; break; }
            }
        }
        g_mask[(rsel ? sb1 : sb0) + ox2] = act ? 1 : 0;
    }
    unsigned bal = __ballot_sync(0xffffffffu, act);
    if (lane == 0 && bal) atomicAdd(&g_nactive, __popc(bal));
}

// ---------------- K3: fold BN params ----------------
__global__ void k_bn(const float* __restrict__ gamma, const float* __restrict__ beta) {
    int c = threadIdx.x;
    if (c >= COUTQ) return;
    float n = (float)max(g_nactive, 1);
    float mean = g_sum[c] / n;
    float var  = g_sumsq[c] / n - mean * mean;
    float rstd = rsqrtf(var + EPSQ);
    float sc   = rstd * gamma[c];
    g_scale[c] = sc;
    g_shift[c] = beta[c] - mean * sc;
}

// ---------------- K4: normalize + relu + mask (in place) ----------------
__global__ void k_final(float* __restrict__ out) {
    int i = blockIdx.x * 256 + threadIdx.x;
    int site = i >> 4;
    int cg   = i & 15;
    float4 v  = ((float4*)out)[i];
    float4 sc = ((const float4*)g_scale)[cg];
    float4 sh = ((const float4*)g_shift)[cg];
    float  m  = g_mask[site] ? 1.f : 0.f;
    v.x = fmaxf(v.x * sc.x + sh.x, 0.f) * m;
    v.y = fmaxf(v.y * sc.y + sh.y, 0.f) * m;
    v.z = fmaxf(v.z * sc.z + sh.z, 0.f) * m;
    v.w = fmaxf(v.w * sc.w + sh.w, 0.f) * m;
    ((float4*)out)[i] = v;
}

// ---------------- launch ----------------
extern "C" void kernel_launch(void* const* d_in, const int* in_sizes, int n_in,
                              void* d_out, int out_size) {
    const float* feats  = (const float*)d_in[0];
    const float* weight = (const float*)d_in[1];
    const float* gamma  = (const float*)d_in[2];
    const float* beta   = (const float*)d_in[3];
    const int*   cb     = (const int*)d_in[4];
    const int*   ct     = (const int*)d_in[5];
    const int*   cy     = (const int*)d_in[6];
    const int*   cx     = (const int*)d_in[7];
    float* out = (float*)d_out;

    cudaFuncSetAttribute(k_conv, cudaFuncAttributeMaxDynamicSharedMemorySize, CONV_DYN_SMEM);

    k_zero<<<NCELL * CIN / 4 / 256, 256>>>();
    k_prepw<<<(27 * COUTQ * 32 + 255) / 256, 256>>>(weight);
    k_scatter<<<NPTS * 32 / 256, 256>>>(feats, cb, ct, cy, cx);
    k_convert<<<NCELL * CIN / 4 / 256, 256>>>();
    k_conv<<<16 * 128, 512, CONV_DYN_SMEM>>>(out);
    k_bn<<<1, 64>>>(gamma, beta);
    k_final<<<NSITE * 16 / 256, 256>>>(out);
}

// round 10
// speedup vs baseline: 1.2722x; 1.0838x over previous
#include <cuda_runtime.h>
#include <cuda_bf16.h>
#include <cstdint>

// ---------------- problem constants ----------------
#define BQ 2
#define TQ 8
#define YQ 128
#define XQ 128
#define CIN 128
#define COUTQ 64
#define YOQ 255
#define XOQ 255
#define NPTS 262144
#define NCELL (BQ*TQ*YQ*XQ)
#define NSITE (BQ*TQ*YOQ*XOQ)
#define NSLAB (BQ*TQ*YQ)
#define EPSQ 1e-5f

// ---------------- device scratch ----------------
__device__ __align__(16) float g_A[(size_t)NCELL * CIN];   // fp32 cell grid
// pre-swizzled tf32 A images: [slab][kq 0..3][cell*128 + swz8] (16KB per quarter)
__device__ __align__(16) unsigned char g_Ab[(size_t)NSLAB * 65536];
__device__ __align__(16) int   g_occ[NCELL];
__device__ unsigned char       g_mask[NSITE];
__device__ __align__(16) float g_sum[COUTQ];
__device__ __align__(16) float g_sumsq[COUTQ];
__device__ int                 g_nactive;
__device__ __align__(16) float g_scale[COUTQ];
__device__ __align__(16) float g_shift[COUTQ];
// pre-swizzled tf32 W images: [ktky 0..8][kq 0..3][kx 0..2][co*128 + swz8] (24KB per (ktky,kq))
__device__ __align__(16) unsigned char g_Wt[9 * 4 * 3 * 8192];

// ---------------- helpers ----------------
__device__ __forceinline__ uint32_t smem_u32(const void* p) {
    uint32_t a;
    asm("{ .reg .u64 t; cvta.to.shared.u64 t, %1; cvt.u32.u64 %0, t; }" : "=r"(a) : "l"(p));
    return a;
}
__device__ __forceinline__ void ldsm4(uint32_t* r, uint32_t addr) {
    asm volatile("ldmatrix.sync.aligned.m8n8.x4.shared.b16 {%0,%1,%2,%3}, [%4];"
        : "=r"(r[0]), "=r"(r[1]), "=r"(r[2]), "=r"(r[3]) : "r"(addr));
}
__device__ __forceinline__ void mma_tf32(float* c, const uint32_t* a, uint32_t b0, uint32_t b1) {
    asm volatile("mma.sync.aligned.m16n8k8.row.col.f32.tf32.tf32.f32 "
        "{%0,%1,%2,%3}, {%4,%5,%6,%7}, {%8,%9}, {%0,%1,%2,%3};"
        : "+f"(c[0]), "+f"(c[1]), "+f"(c[2]), "+f"(c[3])
        : "r"(a[0]), "r"(a[1]), "r"(a[2]), "r"(a[3]), "r"(b0), "r"(b1));
}
__device__ __forceinline__ uint32_t f2tf32(float x) {
    uint32_t t;
    asm("cvt.rna.tf32.f32 %0, %1;" : "=r"(t) : "f"(x));
    return t;
}
__device__ __forceinline__ void bulkcp(uint32_t dst, const void* src, uint32_t bytes, uint32_t mbar) {
    asm volatile("cp.async.bulk.shared::cluster.global.mbarrier::complete_tx::bytes "
                 "[%0], [%1], %2, [%3];"
                 :: "r"(dst), "l"(src), "r"(bytes), "r"(mbar) : "memory");
}
#define MBARRIER_INIT(addr, cnt) \
    asm volatile("mbarrier.init.shared.b64 [%0], %1;" :: "r"((uint32_t)(addr)), "r"((uint32_t)(cnt)) : "memory")
#define MBARRIER_EXPECT_TX(addr, tx) \
    asm volatile("mbarrier.arrive.expect_tx.shared.b64 _, [%0], %1;" \
        :: "r"((uint32_t)(addr)), "r"((uint32_t)(tx)) : "memory")
#define MBARRIER_WAIT_PARITY(addr, par) do { \
    uint32_t _m = (uint32_t)(addr); uint32_t _p = (uint32_t)(par); uint32_t _d; \
    asm volatile("{\n\t.reg .pred p;\n\tmbarrier.try_wait.parity.acquire.cta.shared::cta.b64 p, [%1], %2;\n\tselp.b32 %0, 1, 0, p;\n\t}" \
        : "=r"(_d) : "r"(_m), "r"(_p) : "memory"); \
    if (!_d) { \
        asm volatile("{\n\t.reg .pred P1;\n\tWL_%=:\n\tmbarrier.try_wait.parity.acquire.cta.shared::cta.b64 P1, [%0], %1, 0x989680;\n\t@P1 bra.uni WD_%=;\n\tbra.uni WL_%=;\n\tWD_%=:\n\t}" \
            :: "r"(_m), "r"(_p) : "memory"); \
    } } while (0)

// 128B rows of 8 16B-chunks, XOR-swizzled.
__device__ __forceinline__ uint32_t swz8(int c8, int rs) {
    return (uint32_t)(((c8 ^ rs) & 7) << 4);
}

// ---------------- K0: zero scratch + prep W images (merged so k_conv is 4th launch) ----------------
__global__ void k_zero(const float* __restrict__ W) {
    int idx = blockIdx.x * 256 + threadIdx.x;
    if (idx < NCELL * CIN / 4)
        ((float4*)g_A)[idx] = make_float4(0.f, 0.f, 0.f, 0.f);
    if (idx < NCELL / 4)
        ((int4*)g_occ)[idx] = make_int4(0, 0, 0, 0);
    if (idx < COUTQ) { g_sum[idx] = 0.f; g_sumsq[idx] = 0.f; }
    if (idx == 0) g_nactive = 0;
    // W prep: 27*64*32 = 55296 16B-chunks
    if (idx < 27 * COUTQ * 32) {
        int koff = idx >> 11;
        int r    = idx & 2047;
        int co = r >> 5, c32 = r & 31;
        int kq = c32 >> 3, c8 = c32 & 7;
        int ktky = koff / 3, kx = koff % 3;
        uint32_t v[4];
#pragma unroll
        for (int j = 0; j < 4; j++) {
            int ci = c32 * 4 + j;
            v[j] = f2tf32(W[((size_t)koff * CIN + ci) * COUTQ + co]);
        }
        uint32_t dst = (uint32_t)(((ktky * 4 + kq) * 3 + kx) * 8192)
                     + (uint32_t)(co * 128) + swz8(c8, co & 7);
        *(uint4*)(g_Wt + dst) = make_uint4(v[0], v[1], v[2], v[3]);
    }
}

// ---------------- K1: scatter points ----------------
__global__ void k_scatter(const float* __restrict__ feats,
                          const int* __restrict__ cb, const int* __restrict__ ct,
                          const int* __restrict__ cy, const int* __restrict__ cx) {
    int i = blockIdx.x * 256 + threadIdx.x;
    if (i >= NPTS * 32) return;
    int p  = i >> 5;
    int c4 = i & 31;
    int cell = ((cb[p] * TQ + ct[p]) * YQ + cy[p]) * XQ + cx[p];
    float4 v = ((const float4*)feats)[p * 32 + c4];
    float* dst = &g_A[(size_t)cell * CIN + c4 * 4];
    atomicAdd(dst + 0, v.x);
    atomicAdd(dst + 1, v.y);
    atomicAdd(dst + 2, v.z);
    atomicAdd(dst + 3, v.w);
    if (c4 == 0) atomicAdd(&g_occ[cell], 1);
}

// ---------------- K1b: tf32 + swizzled A quarter-images ----------------
__global__ void k_convert() {
    int i = blockIdx.x * 256 + threadIdx.x;        // NCELL*32 chunks
    int slab = i >> 12;
    int r    = i & 4095;
    int cell = r >> 5, c32 = r & 31;
    int kq = c32 >> 3, c8 = c32 & 7;
    const float4 v = *(const float4*)(g_A + (((size_t)slab * 128 + cell) * CIN + c32 * 4));
    uint4 o = make_uint4(f2tf32(v.x), f2tf32(v.y), f2tf32(v.z), f2tf32(v.w));
    uint32_t dst = (uint32_t)(kq * 16384) + (uint32_t)(cell * 128) + swz8(c8, cell & 7);
    *(uint4*)(g_Ab + (size_t)slab * 65536 + dst) = o;
}

// ---------------- K2: occ-2, quarter-stage bulk-copy tf32 conv ----------------
// CTA = one output row (b,ot,oy), 256 threads, 8 warps = 4 wm x 2 half.
// Stage (40KB): A-quarter [0,16K) (128 cells x 128B swz), W [16K,40K) (kx stride 8K)
#define STG 40960
#define CONV_DYN_SMEM (2 * STG)

__global__ void __launch_bounds__(256, 2) k_conv(float* __restrict__ out) {
    extern __shared__ char smem[];
    __shared__ __align__(8) uint64_t mb[2];
    const uint32_t sb = smem_u32(smem);
    const uint32_t mb0 = smem_u32(&mb[0]), mb1 = smem_u32(&mb[1]);
    const int tid = threadIdx.x, wid = tid >> 5, lane = tid & 31;
    const int half = wid & 1, wm = wid >> 1;

    const int bid = blockIdx.x;
    const int oy = bid % YOQ;
    const int bt = bid / YOQ;
    const int b = bt >> 3, ot = bt & 7;

    // y taps
    int nky, cys[2], kys[2];
    if ((oy & 1) == 0) { nky = 1; cys[0] = oy >> 1;       kys[0] = 1; }
    else               { nky = 2; cys[0] = (oy + 1) >> 1; kys[0] = 0;
                                  cys[1] = (oy - 1) >> 1; kys[1] = 2; }

    // iteration list
    int nIter = 0, slabI[6], ktkyI[6];
    for (int kt = 0; kt < 3; kt++) {
        int ctv = ot + 1 - kt;
        if (ctv < 0 || ctv >= TQ) continue;
        for (int yt = 0; yt < nky; yt++) {
            slabI[nIter] = (b * TQ + ctv) * YQ + cys[yt];
            ktkyI[nIter] = kt * 3 + kys[yt];
            nIter++;
        }
    }
    const int nStage = nIter * 4;

    if (tid == 0) { MBARRIER_INIT(mb0, 1); MBARRIER_INIT(mb1, 1); }
    __syncthreads();

    // ldmatrix geometry (128B rows)
    const int r0 = wm << 5;                  // 32-cell warp tile
    const int matL = lane >> 3, rr = lane & 7;
    const int cSel = matL >> 1;
    int rowA0[2];
    rowA0[0] = r0 + rr + ((matL & 1) << 3);
    rowA0[1] = rowA0[0] + 16;
    const uint32_t bA0[2] = { (uint32_t)rowA0[0] * 128, (uint32_t)rowA0[1] * 128 };
    const uint32_t bA1[2] = { bA0[0] + 128, bA0[1] + 128 };   // rows +1 (row 128 -> garbage, masked)
    const int rs0[2] = { rowA0[0] & 7, rowA0[1] & 7 };
    const int rs1[2] = { (rowA0[0] + 1) & 7, (rowA0[1] + 1) & 7 };
    const int rowB = half * 32 + rr + ((matL & 1) << 3);
    const uint32_t bB0 = (uint32_t)rowB * 128;
    const uint32_t bB1 = bB0 + 16 * 128;
    const int rsB = rowB & 7;

    float accE[2][4][4], accO[2][4][4];
#pragma unroll
    for (int mt = 0; mt < 2; mt++)
#pragma unroll
        for (int i = 0; i < 4; i++)
#pragma unroll
            for (int j = 0; j < 4; j++) { accE[mt][i][j] = 0.f; accO[mt][i][j] = 0.f; }

#define FETCH(ST, DST, MBAR) do { \
    int _it = (ST) >> 2, _kq = (ST) & 3; \
    MBARRIER_EXPECT_TX(MBAR, STG); \
    bulkcp((DST),         g_Ab + (size_t)slabI[_it] * 65536 + _kq * 16384, 16384, MBAR); \
    bulkcp((DST) + 16384, g_Wt + (size_t)(ktkyI[_it] * 4 + _kq) * 24576,   24576, MBAR); \
} while (0)

    if (tid == 0) {
        FETCH(0, sb, mb0);
        FETCH(1, sb + STG, mb1);
    }

    int ph0 = 0, ph1 = 0;
    for (int st = 0; st < nStage; st++) {
        const int buf = st & 1;
        const uint32_t S = sb + (uint32_t)buf * STG;
        if (buf) { MBARRIER_WAIT_PARITY(mb1, ph1); ph1 ^= 1; }
        else     { MBARRIER_WAIT_PARITY(mb0, ph0); ph0 ^= 1; }

        const uint32_t W0 = S + 16384;            // kx=0
        const uint32_t W1 = S + 16384 + 8192;     // kx=1
        const uint32_t W2 = S + 16384 + 16384;    // kx=2
#pragma unroll
        for (int s = 0; s < 4; s++) {
            int ck = 2 * s + cSel;
            uint32_t a0[2][4], a1[2][4];
#pragma unroll
            for (int mt = 0; mt < 2; mt++) {
                ldsm4(a0[mt], S + bA0[mt] + swz8(ck, rs0[mt]));
                ldsm4(a1[mt], S + bA1[mt] + swz8(ck, rs1[mt]));
            }
#pragma unroll
            for (int j2 = 0; j2 < 2; j2++) {
                uint32_t bb = (j2 ? bB1 : bB0) + swz8(ck, rsB);
                uint32_t b1v[4], b2v[4], b0v[4];
                ldsm4(b1v, W1 + bb);
                ldsm4(b2v, W2 + bb);
                ldsm4(b0v, W0 + bb);
#pragma unroll
                for (int mt = 0; mt < 2; mt++) {
                    mma_tf32(accE[mt][2 * j2],     a0[mt], b1v[0], b1v[2]);
                    mma_tf32(accE[mt][2 * j2 + 1], a0[mt], b1v[1], b1v[3]);
                    mma_tf32(accO[mt][2 * j2],     a0[mt], b2v[0], b2v[2]);
                    mma_tf32(accO[mt][2 * j2 + 1], a0[mt], b2v[1], b2v[3]);
                    mma_tf32(accO[mt][2 * j2],     a1[mt], b0v[0], b0v[2]);
                    mma_tf32(accO[mt][2 * j2 + 1], a1[mt], b0v[1], b0v[3]);
                }
            }
        }
        __syncthreads();                      // all readers done with this buffer
        if (st + 2 < nStage && tid == 0)
            FETCH(st + 2, S, buf ? mb1 : mb0);
    }
#undef FETCH

    // ---------------- epilogue: stores + stats ----------------
    const int g = lane >> 2;
    const int n0base = (lane & 3) * 2;
    const int sbase = ((b * TQ + ot) * YOQ + oy) * XOQ;

    float sl[8] = {0,0,0,0,0,0,0,0}, ql[8] = {0,0,0,0,0,0,0,0};
#pragma unroll
    for (int mt = 0; mt < 2; mt++) {
        const int mA = r0 + 16 * mt + g;
        const int mB = mA + 8;
        const bool oddBvalid = (mB != 127);      // ox=255 doesn't exist
#pragma unroll
        for (int nt = 0; nt < 4; nt++) {
            int n0 = half * 32 + nt * 8 + n0base;
            *(float2*)(out + (size_t)(sbase + 2 * mA) * COUTQ + n0) =
                make_float2(accE[mt][nt][0], accE[mt][nt][1]);
            *(float2*)(out + (size_t)(sbase + 2 * mB) * COUTQ + n0) =
                make_float2(accE[mt][nt][2], accE[mt][nt][3]);
            *(float2*)(out + (size_t)(sbase + 2 * mA + 1) * COUTQ + n0) =
                make_float2(accO[mt][nt][0], accO[mt][nt][1]);
            if (oddBvalid)
                *(float2*)(out + (size_t)(sbase + 2 * mB + 1) * COUTQ + n0) =
                    make_float2(accO[mt][nt][2], accO[mt][nt][3]);
#pragma unroll
            for (int c = 0; c < 2; c++) {
                float e0 = accE[mt][nt][c], e2 = accE[mt][nt][2 + c];
                float o0 = accO[mt][nt][c], o2 = oddBvalid ? accO[mt][nt][2 + c] : 0.f;
                sl[nt * 2 + c] += e0 + e2 + o0 + o2;
                ql[nt * 2 + c] += e0 * e0 + e2 * e2 + o0 * o0 + o2 * o2;
            }
        }
    }
#pragma unroll
    for (int d = 4; d <= 16; d <<= 1) {
#pragma unroll
        for (int i = 0; i < 8; i++) {
            sl[i] += __shfl_xor_sync(0xffffffffu, sl[i], d);
            ql[i] += __shfl_xor_sync(0xffffffffu, ql[i], d);
        }
    }
    __syncthreads();                          // pipeline drained; reuse smem
    float* redS = (float*)smem;               // [8 warps][4][8]
    float* redQ = (float*)(smem + 8 * 4 * 8 * 4);
    if (lane < 4) {
#pragma unroll
        for (int i = 0; i < 8; i++) {
            redS[(wid * 4 + lane) * 8 + i] = sl[i];
            redQ[(wid * 4 + lane) * 8 + i] = ql[i];
        }
    }
    __syncthreads();
    if (tid < COUTQ) {
        // cout = half*32 + nt*8 + c4*2 + cc ; warps with this half: wid = wm*2 + h2
        int h2 = tid >> 5, nt = (tid >> 3) & 3, c4 = (tid >> 1) & 3, cc = tid & 1;
        int idx = nt * 2 + cc;
        float S = 0.f, Q = 0.f;
#pragma unroll
        for (int wmx = 0; wmx < 4; wmx++) {
            int w = wmx * 2 + h2;
            S += redS[(w * 4 + c4) * 8 + idx];
            Q += redQ[(w * 4 + c4) * 8 + idx];
        }
        atomicAdd(&g_sum[tid], S);
        atomicAdd(&g_sumsq[tid], Q);
    }

    // ---------------- active-site mask ----------------
    bool act = false;
    if (tid < XOQ) {
        int ox2 = tid;
        int xc[2]; int nxc = 0;
        if ((ox2 & 1) == 0) { xc[nxc++] = ox2 >> 1; }
        else {
            int c0 = (ox2 + 1) >> 1;
            if (c0 < XQ) xc[nxc++] = c0;
            xc[nxc++] = (ox2 - 1) >> 1;
        }
        for (int kt = 0; kt < 3 && !act; kt++) {
            int ctv = ot + 1 - kt;
            if (ctv < 0 || ctv >= TQ) continue;
            for (int yt = 0; yt < nky && !act; yt++) {
                int cb2 = ((b * TQ + ctv) * YQ + cys[yt]) * XQ;
                for (int xi = 0; xi < nxc; xi++)
                    if (g_occ[cb2 + xc[xi]] > 0) { act = true; break; }
            }
        }
        g_mask[sbase + ox2] = act ? 1 : 0;
    }
    unsigned bal = __ballot_sync(0xffffffffu, act);
    if (lane == 0 && bal) atomicAdd(&g_nactive, __popc(bal));
}

// ---------------- K3: fold BN params ----------------
__global__ void k_bn(const float* __restrict__ gamma, const float* __restrict__ beta) {
    int c = threadIdx.x;
    if (c >= COUTQ) return;
    float n = (float)max(g_nactive, 1);
    float mean = g_sum[c] / n;
    float var  = g_sumsq[c] / n - mean * mean;
    float rstd = rsqrtf(var + EPSQ);
    float sc   = rstd * gamma[c];
    g_scale[c] = sc;
    g_shift[c] = beta[c] - mean * sc;
}

// ---------------- K4: normalize + relu + mask (in place) ----------------
__global__ void k_final(float* __restrict__ out) {
    int i = blockIdx.x * 256 + threadIdx.x;
    int site = i >> 4;
    int cg   = i & 15;
    float4 v  = ((float4*)out)[i];
    float4 sc = ((const float4*)g_scale)[cg];
    float4 sh = ((const float4*)g_shift)[cg];
    float  m  = g_mask[site] ? 1.f : 0.f;
    v.x = fmaxf(v.x * sc.x + sh.x, 0.f) * m;
    v.y = fmaxf(v.y * sc.y + sh.y, 0.f) * m;
    v.z = fmaxf(v.z * sc.z + sh.z, 0.f) * m;
    v.w = fmaxf(v.w * sc.w + sh.w, 0.f) * m;
    ((float4*)out)[i] = v;
}

// ---------------- launch ----------------
extern "C" void kernel_launch(void* const* d_in, const int* in_sizes, int n_in,
                              void* d_out, int out_size) {
    const float* feats  = (const float*)d_in[0];
    const float* weight = (const float*)d_in[1];
    const float* gamma  = (const float*)d_in[2];
    const float* beta   = (const float*)d_in[3];
    const int*   cb     = (const int*)d_in[4];
    const int*   ct     = (const int*)d_in[5];
    const int*   cy     = (const int*)d_in[6];
    const int*   cx     = (const int*)d_in[7];
    float* out = (float*)d_out;

    cudaFuncSetAttribute(k_conv, cudaFuncAttributeMaxDynamicSharedMemorySize, CONV_DYN_SMEM);

    k_zero<<<NCELL * CIN / 4 / 256, 256>>>(weight);
    k_scatter<<<NPTS * 32 / 256, 256>>>(feats, cb, ct, cy, cx);
    k_convert<<<NCELL * 32 / 256, 256>>>();
    k_conv<<<BQ * TQ * YOQ, 256, CONV_DYN_SMEM>>>(out);
    k_bn<<<1, 64>>>(gamma, beta);
    k_final<<<NSITE * 16 / 256, 256>>>(out);
}